// round 1
// baseline (speedup 1.0000x reference)
#include <cuda_runtime.h>
#include <math.h>

// SpatialGRU wavefront implementation (fp32 baseline).
// B=128, C=32, L=R=80, U=128, D=C+3U=416.
// Recurrence: cell(l,r) needs h(l,r-1) [left], h(l-1,r) [top], h(l-1,r-1) [diag].
// Anti-diagonal wavefront: one kernel launch per diagonal d=l+r (159 launches).
// Per-cell math fused into one 1024x416 GEMM (Wr|Wz|[0,Wij]) + one 128x384 GEMM (WU).

namespace {
constexpr int B = 128, C = 32, L = 80, R = 80, U = 128;
constexpr int D = 416;       // C + 3U (q = [h_top, h_left, h_diag, s])
constexpr int NGATE = 1024;  // 3U (r) + 4U (z) + U (s@Wij)
constexpr int MB = 32;       // batch rows per CTA (4 CTAs per cell)
constexpr int KB = 32;       // k-block staged to smem
constexpr int WSP = 44;      // smem W pitch (floats): conflict-free for lane-stride-1-row LDS.128

// shared memory layout (in floats)
constexpr int SM_A  = 0;                  // sA  [MB][D]       : 13312
constexpr int SM_W  = SM_A + MB * D;      // sW  [256][WSP]    : 11264
constexpr int SM_RT = SM_W + 256 * WSP;   // sRt [MB][384]     : 12288  (r * h_cat)
constexpr int SM_Z  = SM_RT + MB * 384;   // sZ  [4][MB][128]  : 16384  (z logits)
constexpr int SM_P  = SM_Z + 4 * MB * 128;// sP  [MB][128]     : 4096   (s@Wij + bij)
constexpr int SM_FLOATS = SM_P + MB * 128;         // 57344 floats = 229376 B
}

__device__ float g_W[NGATE * D];   // fused gate weights
__device__ float g_b[NGATE];       // fused gate bias
__device__ float g_x[L * R * B * C]; // transposed inputs (l,r,b,c)
__device__ float g_H[3][L][B * U];   // rotating diagonal h buffers, indexed by l

// ---------------------------------------------------------------------------
// Build fused weight matrix: rows 0..383 = Wr, 384..895 = Wz,
// rows 896..1023 = [zeros(384) | Wij] so chunk 7 of the gates GEMM emits s@Wij^T.
__global__ void prep_kernel(const float* __restrict__ Wr, const float* __restrict__ br,
                            const float* __restrict__ Wz, const float* __restrict__ bz,
                            const float* __restrict__ Wij, const float* __restrict__ bij) {
    int stride = gridDim.x * blockDim.x;
    int idx0 = blockIdx.x * blockDim.x + threadIdx.x;
    for (int i = idx0; i < NGATE * D; i += stride) {
        int j = i / D, k = i - j * D;
        float v;
        if (j < 384)      v = Wr[j * D + k];
        else if (j < 896) v = Wz[(j - 384) * D + k];
        else              v = (k >= 384) ? Wij[(j - 896) * C + (k - 384)] : 0.0f;
        g_W[i] = v;
    }
    for (int i = idx0; i < NGATE; i += stride)
        g_b[i] = (i < 384) ? br[i] : (i < 896 ? bz[i - 384] : bij[i - 896]);
}

// ---------------------------------------------------------------------------
// (B,C,L,R) -> (L,R,B,C) so each cell's s-tile is contiguous per batch row.
__global__ void transpose_kernel(const float* __restrict__ in) {
    __shared__ float tile[C][R + 1];
    int b = blockIdx.x, l = blockIdx.y;
    for (int i = threadIdx.x; i < C * R; i += blockDim.x) {
        int c = i / R, r = i - c * R;
        tile[c][r] = in[((b * C + c) * L + l) * R + r];
    }
    __syncthreads();
    for (int i = threadIdx.x; i < R * C; i += blockDim.x) {
        int r = i >> 5, c = i & 31;
        g_x[((l * R + r) * B + b) * C + c] = tile[c][r];
    }
}

// ---------------------------------------------------------------------------
// One CTA = (cell on diagonal d, 32-row batch tile).
// Stage 1: gates[32][1024] = [hT|hL|hD|s] @ g_W^T + g_b   (4 chunks of 256 cols)
// Stage 2: hU[32][128] = (r .* h_cat) @ WU^T, then h_hat, softmax combine, write h.
__global__ void __launch_bounds__(256, 1)
cell_kernel(int d, int lmin, const float* __restrict__ WU) {
    extern __shared__ float sm[];
    float* sA  = sm + SM_A;
    float* sW  = sm + SM_W;
    float* sRt = sm + SM_RT;
    float* sZ  = sm + SM_Z;
    float* sP  = sm + SM_P;

    const int cell = blockIdx.x >> 2;
    const int bt   = blockIdx.x & 3;
    const int l = lmin + cell;
    const int r = d - l;
    const int bs = bt * MB;

    const int tid = threadIdx.x;
    const int tj = tid & 31;   // lane: j within group (also warp lane)
    const int tb = tid >> 5;   // warp: which 4-row batch group

    // diag buffer rotation: d-1 -> (d+2)%3, d-2 -> (d+1)%3, write -> d%3
    const float* hT = (l > 0)          ? g_H[(d + 2) % 3][l - 1] : (const float*)nullptr;
    const float* hL = (r > 0)          ? g_H[(d + 2) % 3][l]     : (const float*)nullptr;
    const float* hD = (l > 0 && r > 0) ? g_H[(d + 1) % 3][l - 1] : (const float*)nullptr;
    float* Hout = g_H[d % 3][l];

    // Load A tile: q layout cols [0:128)=h_top, [128:256)=h_left, [256:384)=h_diag, [384:416)=s
    for (int i = tid; i < MB * U; i += 256) {
        int b = i >> 7, u = i & 127;
        int gi = (bs + b) * U + u;
        sA[b * D + u]       = hT ? hT[gi] : 0.0f;
        sA[b * D + 128 + u] = hL ? hL[gi] : 0.0f;
        sA[b * D + 256 + u] = hD ? hD[gi] : 0.0f;
    }
    for (int i = tid; i < MB * C; i += 256) {
        int b = i >> 5, c = i & 31;
        sA[b * D + 384 + c] = g_x[((l * R + r) * B + (bs + b)) * C + c];
    }
    // first __syncthreads inside the k-block loop covers these writes

    // ---- Stage 1 ----
    for (int ch = 0; ch < 4; ++ch) {
        float acc[4][8];
        #pragma unroll
        for (int bb = 0; bb < 4; ++bb)
            #pragma unroll
            for (int jj = 0; jj < 8; ++jj) acc[bb][jj] = 0.0f;
        const int jbase = ch * 256;

        for (int kb = 0; kb < D; kb += KB) {
            __syncthreads();
            // stage W block [jbase..jbase+255][kb..kb+31] into sW
            #pragma unroll
            for (int p = 0; p < 8; ++p) {
                int row = (tid >> 3) + p * 32;
                int kq  = (tid & 7) * 4;
                float4 wv = *(const float4*)&g_W[(jbase + row) * D + kb + kq];
                *(float4*)&sW[row * WSP + kq] = wv;
            }
            __syncthreads();
            #pragma unroll
            for (int kq = 0; kq < KB; kq += 4) {
                float4 a[4];
                #pragma unroll
                for (int bb = 0; bb < 4; ++bb)
                    a[bb] = *(const float4*)&sA[(tb * 4 + bb) * D + kb + kq];
                float4 w[8];
                #pragma unroll
                for (int jj = 0; jj < 8; ++jj)
                    w[jj] = *(const float4*)&sW[(jj * 32 + tj) * WSP + kq];
                #pragma unroll
                for (int bb = 0; bb < 4; ++bb)
                    #pragma unroll
                    for (int jj = 0; jj < 8; ++jj) {
                        acc[bb][jj] += a[bb].x * w[jj].x;
                        acc[bb][jj] += a[bb].y * w[jj].y;
                        acc[bb][jj] += a[bb].z * w[jj].z;
                        acc[bb][jj] += a[bb].w * w[jj].w;
                    }
            }
        }
        // activation / scatter
        #pragma unroll
        for (int bb = 0; bb < 4; ++bb) {
            int b = tb * 4 + bb;
            #pragma unroll
            for (int jj = 0; jj < 8; ++jj) {
                int j = jbase + jj * 32 + tj;
                float v = acc[bb][jj] + g_b[j];
                if (j < 384) {
                    // r gate: r[:,0:128]*h_left, [128:256)*h_top, [256:384)*h_diag
                    float rg = 1.0f / (1.0f + expf(-v));
                    int u = j & 127;
                    int part = j >> 7;
                    int off = (part == 0) ? 128 : (part == 1 ? 0 : 256);
                    sRt[b * 384 + j] = rg * sA[b * D + off + u];
                } else if (j < 896) {
                    int jz = j - 384;  // group 0:zi 1:zl 2:zt 3:zd
                    sZ[((jz >> 7) * MB + b) * 128 + (jz & 127)] = v;
                } else {
                    sP[b * 128 + (j - 896)] = v;  // s@Wij^T + bij
                }
            }
        }
    }

    // ---- Stage 2: hU = sRt @ WU^T ----
    float acc2[4][4];
    #pragma unroll
    for (int bb = 0; bb < 4; ++bb)
        #pragma unroll
        for (int jj = 0; jj < 4; ++jj) acc2[bb][jj] = 0.0f;

    for (int kb = 0; kb < 384; kb += KB) {
        __syncthreads();   // also guards sRt writes before first read
        #pragma unroll
        for (int p = 0; p < 4; ++p) {
            int row = (tid >> 3) + p * 32;
            int kq  = (tid & 7) * 4;
            float4 wv = *(const float4*)&WU[row * 384 + kb + kq];
            *(float4*)&sW[row * WSP + kq] = wv;
        }
        __syncthreads();
        #pragma unroll
        for (int kq = 0; kq < KB; kq += 4) {
            float4 a[4];
            #pragma unroll
            for (int bb = 0; bb < 4; ++bb)
                a[bb] = *(const float4*)&sRt[(tb * 4 + bb) * 384 + kb + kq];
            float4 w[4];
            #pragma unroll
            for (int jj = 0; jj < 4; ++jj)
                w[jj] = *(const float4*)&sW[(jj * 32 + tj) * WSP + kq];
            #pragma unroll
            for (int bb = 0; bb < 4; ++bb)
                #pragma unroll
                for (int jj = 0; jj < 4; ++jj) {
                    acc2[bb][jj] += a[bb].x * w[jj].x;
                    acc2[bb][jj] += a[bb].y * w[jj].y;
                    acc2[bb][jj] += a[bb].z * w[jj].z;
                    acc2[bb][jj] += a[bb].w * w[jj].w;
                }
        }
    }

    // ---- finale: h_hat, softmax over {zi,zl,zt,zd}, combine, write ----
    #pragma unroll
    for (int bb = 0; bb < 4; ++bb) {
        int b = tb * 4 + bb;
        #pragma unroll
        for (int jj = 0; jj < 4; ++jj) {
            int u = jj * 32 + tj;
            float hhat = tanhf(sP[b * 128 + u] + acc2[bb][jj]);
            float zi = sZ[(0 * MB + b) * 128 + u];
            float zl = sZ[(1 * MB + b) * 128 + u];
            float zt = sZ[(2 * MB + b) * 128 + u];
            float zd = sZ[(3 * MB + b) * 128 + u];
            float m = fmaxf(fmaxf(zi, zl), fmaxf(zt, zd));
            float ei = expf(zi - m), el = expf(zl - m), et = expf(zt - m), ed = expf(zd - m);
            float hLv = sA[b * D + 128 + u];
            float hTv = sA[b * D + u];
            float hDv = sA[b * D + 256 + u];
            Hout[(bs + b) * U + u] =
                (ei * hhat + el * hLv + et * hTv + ed * hDv) / (ei + el + et + ed);
        }
    }
}

// ---------------------------------------------------------------------------
__global__ void out_kernel(float* __restrict__ out) {
    int i = blockIdx.x * blockDim.x + threadIdx.x;
    if (i < B * U) out[i] = g_H[(L + R - 2) % 3][L - 1][i];
}

extern "C" void kernel_launch(void* const* d_in, const int* in_sizes, int n_in,
                              void* d_out, int out_size) {
    const float* inputs = (const float*)d_in[0];
    const float* Wr  = (const float*)d_in[1];
    const float* br  = (const float*)d_in[2];
    const float* Wz  = (const float*)d_in[3];
    const float* bz  = (const float*)d_in[4];
    const float* Wij = (const float*)d_in[5];
    const float* bij = (const float*)d_in[6];
    const float* WU  = (const float*)d_in[7];

    cudaFuncSetAttribute(cell_kernel, cudaFuncAttributeMaxDynamicSharedMemorySize,
                         SM_FLOATS * (int)sizeof(float));

    prep_kernel<<<128, 256>>>(Wr, br, Wz, bz, Wij, bij);
    transpose_kernel<<<dim3(B, L), 256>>>(inputs);

    for (int d = 0; d < L + R - 1; ++d) {
        int lmin = d - (R - 1); if (lmin < 0) lmin = 0;
        int lmax = (d < L - 1) ? d : (L - 1);
        int n = lmax - lmin + 1;
        cell_kernel<<<n * 4, 256, SM_FLOATS * sizeof(float)>>>(d, lmin, WU);
    }
    out_kernel<<<64, 256>>>((float*)d_out);
}